// round 10
// baseline (speedup 1.0000x reference)
#include <cuda_runtime.h>
#include <cuda_fp16.h>
#include <math.h>
#include <stdint.h>

// Problem constants
constexpr int Bb    = 2;
constexpr int Ss    = 1024;
constexpr int Dd    = 1024;
constexpr int Hh    = 8;
constexpr int HD    = 128;
constexpr int DEPTH = 8;
constexpr int FF    = 4096;
constexpr int BS    = Bb * Ss;      // 2048
constexpr int RSPLIT = 32;

// Scratch (device globals: allocation-free)
__device__ float  g_x  [BS * Dd];
__device__ __half g_xn [BS * Dd];
__device__ __half g_qkv[(size_t)BS * 3 * Dd];            // q | k | v packed (half)
__device__ __half g_wqkvT[(size_t)DEPTH * 3 * Dd * Dd];  // [Wq|Wkv]^T [3D][D] half
__device__ __half g_woT [(size_t)DEPTH * Dd * Dd];       // Wo^T  [D][D] half
__device__ __half g_w1T [(size_t)DEPTH * FF * Dd];       // W1^T  [FF][D] half
__device__ __half g_w2T [(size_t)DEPTH * Dd * FF];       // W2^T  [D][FF] half
__device__ __half g_attn[(size_t)Bb * Hh * Ss * Ss];     // 32 MB
__device__ __half g_y  [BS * Dd];
__device__ __half g_ff [(size_t)BS * FF];
__device__ float  g_red[(size_t)4 * BS * Dd];            // split-K partials (fp32)
__device__ float  g_part[RSPLIT * Bb * Ss];

// ---------------------------------------------------------------- mma / ldmatrix
__device__ __forceinline__ void mma_f16(float* c, const unsigned* a, const unsigned* b) {
    asm volatile(
        "mma.sync.aligned.m16n8k16.row.col.f32.f16.f16.f32 "
        "{%0,%1,%2,%3}, {%4,%5,%6,%7}, {%8,%9}, {%0,%1,%2,%3};"
        : "+f"(c[0]), "+f"(c[1]), "+f"(c[2]), "+f"(c[3])
        : "r"(a[0]), "r"(a[1]), "r"(a[2]), "r"(a[3]), "r"(b[0]), "r"(b[1]));
}
__device__ __forceinline__ void ldsm4(unsigned& r0, unsigned& r1, unsigned& r2,
                                      unsigned& r3, unsigned addr) {
    asm volatile("ldmatrix.sync.aligned.m8n8.x4.shared.b16 {%0,%1,%2,%3}, [%4];"
                 : "=r"(r0), "=r"(r1), "=r"(r2), "=r"(r3) : "r"(addr));
}
__device__ __forceinline__ void ldsm4t(unsigned& r0, unsigned& r1, unsigned& r2,
                                       unsigned& r3, unsigned addr) {
    asm volatile("ldmatrix.sync.aligned.m8n8.x4.trans.shared.b16 {%0,%1,%2,%3}, [%4];"
                 : "=r"(r0), "=r"(r1), "=r"(r2), "=r"(r3) : "r"(addr));
}
__device__ __forceinline__ void cp_async16(unsigned saddr, const void* gptr) {
    asm volatile("cp.async.cg.shared.global [%0], [%1], 16;"
                 :: "r"(saddr), "l"(gptr));
}
#define CP_COMMIT() asm volatile("cp.async.commit_group;")
#define CP_WAIT1()  asm volatile("cp.async.wait_group 1;")

// ---------------------------------------------------------------- fp16 tensor-core GEMM
// C[M,N] = epi(alpha * A[M,K] @ B), A half [M][K].
// TRANSB: B half [N][K] (ldb = K-stride). else B half [K][N] (AV path).
// EPI: 0 = store, 2 = gelu.  OUTHALF: store half2, else fp32 (split-K partials).
// causal: 0 none, 1 = skip tiles above diagonal, 2 = K-trim.
#define BM 128
#define BN 128
#define BKH 32          // halves per k-tile
#define AL 40           // A / B(trans) row length in halves: 80B rows, conflict-free ldsm
#define BLN 136         // B(non-trans) [k][n] row length in halves: 272B rows
#define STAGES 3
constexpr int AH_ST = BM * AL;                 // 5120 halves
constexpr int BH_ST = 5120;                    // max(128*40, 32*136)
constexpr int GEMM_SMEM = STAGES * (AH_ST + BH_ST) * 2;   // 61440 B -> 3 CTAs/SM

template<int EPI, bool TRANSB, bool OUTHALF>
__global__ __launch_bounds__(128, 3) void gemm_h(
    const __half* __restrict__ A, const __half* __restrict__ Bg,
    void* __restrict__ Cv,
    int K, int lda, int ldb, int ldc,
    long long sAo, long long sAi, long long sBo, long long sBi,
    long long sCo, long long sCi, int zdiv,
    float alpha, int causal)
{
    const int bm = blockIdx.y * BM;
    const int bn = blockIdx.x * BN;
    if (causal == 1 && bn >= bm + BM) return;
    const int Keff = (causal == 2) ? min(K, bm + BM) : K;

    const int z  = blockIdx.z;
    const int zo = z / zdiv;
    const int zi = z - zo * zdiv;
    A  += zo * sAo + zi * sAi;
    Bg += zo * sBo + zi * sBi;
    const long long coff = zo * sCo + zi * sCi;
    __half* Ch = (__half*)Cv + coff;
    float*  Cf = (float*)Cv + coff;

    extern __shared__ __align__(16) char smem_raw[];
    const unsigned asb = (unsigned)__cvta_generic_to_shared(smem_raw);
    const unsigned bsb = asb + (unsigned)(STAGES * AH_ST * 2);

    const int tid  = threadIdx.x;
    const int lane = tid & 31;
    const int warp = tid >> 5;
    const int wm   = (warp & 1) * 64;       // warp tile 64(M) x 64(N)
    const int wn   = (warp >> 1) * 64;
    const int g    = lane >> 2;
    const int t    = lane & 3;

    const int lp = lane >> 3;
    const int lr = lane & 7;
    const int aRowOff  = (lp & 1) * 8 + lr;
    const int aColOff  = (lp >> 1) * 8;         // halves
    const int bRowOff  = (lp >> 1) * 8 + lr;    // trans-B frag (n rows)
    const int bColOff  = (lp & 1) * 8;
    const int ntRowOff = (lp & 1) * 8 + lr;     // non-trans B (k rows)
    const int ntColOff = (lp >> 1) * 8;

    float acc[4][8][4];
    #pragma unroll
    for (int i = 0; i < 4; i++)
        #pragma unroll
        for (int j = 0; j < 8; j++)
            #pragma unroll
            for (int r = 0; r < 4; r++) acc[i][j][r] = 0.f;

    auto issue = [&](int s, int k0) {
        const unsigned aB = asb + (unsigned)(s * AH_ST * 2);
        #pragma unroll
        for (int h = 0; h < 4; h++) {
            int row = (tid >> 2) + 32 * h;
            cp_async16(aB + (unsigned)((row * AL + (tid & 3) * 8) * 2),
                       &A[(long long)(bm + row) * lda + k0 + (tid & 3) * 8]);
        }
        const unsigned bB = bsb + (unsigned)(s * BH_ST * 2);
        if (TRANSB) {
            #pragma unroll
            for (int h = 0; h < 4; h++) {
                int row = (tid >> 2) + 32 * h;
                cp_async16(bB + (unsigned)((row * AL + (tid & 3) * 8) * 2),
                           &Bg[(long long)(bn + row) * ldb + k0 + (tid & 3) * 8]);
            }
        } else {
            #pragma unroll
            for (int h = 0; h < 4; h++) {
                int idx = h * 128 + tid;
                int kr  = idx >> 4;
                int ch  = idx & 15;
                cp_async16(bB + (unsigned)((kr * BLN + ch * 8) * 2),
                           &Bg[(long long)(k0 + kr) * ldb + bn + ch * 8]);
            }
        }
    };

    auto compute = [&](int p) {
        const unsigned abase = asb + (unsigned)(p * AH_ST * 2)
                             + (unsigned)(((wm + aRowOff) * AL + aColOff) * 2);
        unsigned bbase;
        if (TRANSB)
            bbase = bsb + (unsigned)(p * BH_ST * 2)
                  + (unsigned)(((wn + bRowOff) * AL + bColOff) * 2);
        else
            bbase = bsb + (unsigned)(p * BH_ST * 2)
                  + (unsigned)((ntRowOff * BLN + wn + ntColOff) * 2);
        #pragma unroll
        for (int ks = 0; ks < 2; ks++) {
            const int kk = ks * 16;
            unsigned af[4][4], bf[8][2];
            #pragma unroll
            for (int i = 0; i < 4; i++)
                ldsm4(af[i][0], af[i][1], af[i][2], af[i][3],
                      abase + (unsigned)((i * 16 * AL + kk) * 2));
            if (TRANSB) {
                #pragma unroll
                for (int jp = 0; jp < 4; jp++) {
                    unsigned r0, r1, r2, r3;
                    ldsm4(r0, r1, r2, r3, bbase + (unsigned)((jp * 16 * AL + kk) * 2));
                    bf[2 * jp][0] = r0; bf[2 * jp][1] = r1;
                    bf[2 * jp + 1][0] = r2; bf[2 * jp + 1][1] = r3;
                }
            } else {
                #pragma unroll
                for (int jp = 0; jp < 4; jp++) {
                    unsigned r0, r1, r2, r3;
                    ldsm4t(r0, r1, r2, r3,
                           bbase + (unsigned)((kk * BLN + jp * 16) * 2));
                    bf[2 * jp][0] = r0; bf[2 * jp][1] = r1;
                    bf[2 * jp + 1][0] = r2; bf[2 * jp + 1][1] = r3;
                }
            }
            #pragma unroll
            for (int i = 0; i < 4; i++)
                #pragma unroll
                for (int j = 0; j < 8; j++)
                    mma_f16(acc[i][j], af[i], bf[j]);
        }
    };

    const int nk = Keff / BKH;
    #pragma unroll
    for (int s = 0; s < STAGES - 1; s++) {        // prefetch 2 tiles
        if (s < nk) issue(s, s * BKH);
        CP_COMMIT();
    }
    for (int kt = 0; kt < nk; kt++) {
        CP_WAIT1();                                // tile kt landed (kt+1 in flight)
        __syncthreads();
        compute(kt % STAGES);
        if (kt + STAGES - 1 < nk)
            issue((kt + STAGES - 1) % STAGES, (kt + STAGES - 1) * BKH);
        CP_COMMIT();
    }

    // Epilogue
    #pragma unroll
    for (int i = 0; i < 4; i++) {
        #pragma unroll
        for (int j = 0; j < 8; j++) {
            const long long row = bm + wm + i * 16 + g;
            const int       col = bn + wn + j * 8 + 2 * t;
            float2 v0 = make_float2(acc[i][j][0] * alpha, acc[i][j][1] * alpha);
            float2 v1 = make_float2(acc[i][j][2] * alpha, acc[i][j][3] * alpha);
            if (EPI == 2) {
                const float c = 0.70710678118654752f;
                v0.x = 0.5f * v0.x * erfcf(-v0.x * c);
                v0.y = 0.5f * v0.y * erfcf(-v0.y * c);
                v1.x = 0.5f * v1.x * erfcf(-v1.x * c);
                v1.y = 0.5f * v1.y * erfcf(-v1.y * c);
            }
            if (OUTHALF) {
                *(__half2*)&Ch[row * (long long)ldc + col]       = __floats2half2_rn(v0.x, v0.y);
                *(__half2*)&Ch[(row + 8) * (long long)ldc + col] = __floats2half2_rn(v1.x, v1.y);
            } else {
                *(float2*)&Cf[row * (long long)ldc + col]       = v0;
                *(float2*)&Cf[(row + 8) * (long long)ldc + col] = v1;
            }
        }
    }
}

// ---------------------------------------------------------------- split-K reduce (+optional snapshot)
template<int P, bool BIAS, bool SNAP>
__global__ __launch_bounds__(256) void reduce_add_k(
    const float4* __restrict__ part, float4* __restrict__ x,
    const float* __restrict__ bias, float4* __restrict__ st, int layer)
{
    const int i = blockIdx.x * 256 + threadIdx.x;
    constexpr int N4 = BS * Dd / 4;
    float4 s = part[i];
    #pragma unroll
    for (int p = 1; p < P; p++) {
        float4 v = part[(size_t)p * N4 + i];
        s.x += v.x; s.y += v.y; s.z += v.z; s.w += v.w;
    }
    if (BIAS) {
        float4 bb = ((const float4*)bias)[i & (Dd / 4 - 1)];
        s.x += bb.x; s.y += bb.y; s.z += bb.z; s.w += bb.w;
    }
    float4 o = x[i];
    o.x += s.x; o.y += s.y; o.z += s.z; o.w += s.w;
    x[i] = o;
    if (SNAP)
        st[((long long)(i >> 8) * DEPTH + layer) * 256 + (i & 255)] = o;
}

// ---------------------------------------------------------------- transpose + cvt to half
__global__ __launch_bounds__(256) void transpose_cvt_k(
    const float* __restrict__ src, __half* __restrict__ dst,
    int R, int C, long long sSrc, long long sDst)
{
    __shared__ float tile[32][33];
    src += blockIdx.z * sSrc;
    dst += blockIdx.z * sDst;
    const int c0 = blockIdx.x * 32, r0 = blockIdx.y * 32;
    const int tx = threadIdx.x & 31, ty = threadIdx.x >> 5;
    #pragma unroll
    for (int dy = 0; dy < 32; dy += 8)
        tile[ty + dy][tx] = src[(long long)(r0 + ty + dy) * C + c0 + tx];
    __syncthreads();
    #pragma unroll
    for (int dy = 0; dy < 32; dy += 8)
        dst[(long long)(c0 + ty + dy) * R + r0 + tx] = __float2half_rn(tile[tx][ty + dy]);
}

// ---------------------------------------------------------------- LayerNorm
template<bool OUTH>
__global__ __launch_bounds__(256) void ln_k(
    const float* __restrict__ x, const float* __restrict__ g,
    const float* __restrict__ b, void* __restrict__ outv)
{
    __shared__ float sm0[8], sm1[8];
    const int row = blockIdx.x, tid = threadIdx.x;
    float4 v = ((const float4*)(x + (long long)row * Dd))[tid];
    float s  = v.x + v.y + v.z + v.w;
    float s2 = v.x * v.x + v.y * v.y + v.z * v.z + v.w * v.w;
    #pragma unroll
    for (int o = 16; o > 0; o >>= 1) {
        s  += __shfl_xor_sync(0xffffffffu, s,  o);
        s2 += __shfl_xor_sync(0xffffffffu, s2, o);
    }
    if ((tid & 31) == 0) { sm0[tid >> 5] = s; sm1[tid >> 5] = s2; }
    __syncthreads();
    if (tid < 32) {
        s  = (tid < 8) ? sm0[tid] : 0.f;
        s2 = (tid < 8) ? sm1[tid] : 0.f;
        #pragma unroll
        for (int o = 4; o > 0; o >>= 1) {
            s  += __shfl_xor_sync(0xffffffffu, s,  o);
            s2 += __shfl_xor_sync(0xffffffffu, s2, o);
        }
        if (tid == 0) { sm0[0] = s; sm1[0] = s2; }
    }
    __syncthreads();
    const float mean = sm0[0] * (1.f / Dd);
    const float var  = sm1[0] * (1.f / Dd) - mean * mean;
    const float rstd = rsqrtf(var + 1e-5f);
    float4 gg = ((const float4*)g)[tid];
    float4 bb = ((const float4*)b)[tid];
    float4 o;
    o.x = (v.x - mean) * rstd * gg.x + bb.x;
    o.y = (v.y - mean) * rstd * gg.y + bb.y;
    o.z = (v.z - mean) * rstd * gg.z + bb.z;
    o.w = (v.w - mean) * rstd * gg.w + bb.w;
    if (OUTH) {
        __half2* oh = (__half2*)((__half*)outv + (long long)row * Dd);
        oh[2 * tid]     = __floats2half2_rn(o.x, o.y);
        oh[2 * tid + 1] = __floats2half2_rn(o.z, o.w);
    } else {
        ((float4*)((float*)outv + (long long)row * Dd))[tid] = o;
    }
}

// ---------------------------------------------------------------- Softmax (half in/out, fp32 math)
__global__ __launch_bounds__(256) void softmax_k(__half* __restrict__ attn)
{
    __shared__ float sm[8];
    const int row = blockIdx.x;
    const int q   = row & (Ss - 1);
    __half* p = attn + (long long)row * Ss;
    const int tid = threadIdx.x;
    const int k0  = tid * 4;
    __half2 h0 = ((const __half2*)p)[2 * tid];
    __half2 h1 = ((const __half2*)p)[2 * tid + 1];
    float4 v = make_float4(__low2float(h0), __high2float(h0),
                           __low2float(h1), __high2float(h1));

    float m = -1e30f;
    if (k0 + 0 <= q) m = fmaxf(m, v.x);
    if (k0 + 1 <= q) m = fmaxf(m, v.y);
    if (k0 + 2 <= q) m = fmaxf(m, v.z);
    if (k0 + 3 <= q) m = fmaxf(m, v.w);
    #pragma unroll
    for (int o = 16; o > 0; o >>= 1) m = fmaxf(m, __shfl_xor_sync(0xffffffffu, m, o));
    if ((tid & 31) == 0) sm[tid >> 5] = m;
    __syncthreads();
    if (tid < 32) {
        float t = (tid < 8) ? sm[tid] : -1e30f;
        #pragma unroll
        for (int o = 4; o > 0; o >>= 1) t = fmaxf(t, __shfl_xor_sync(0xffffffffu, t, o));
        if (tid == 0) sm[0] = t;
    }
    __syncthreads();
    m = sm[0];
    __syncthreads();

    float4 e;
    e.x = (k0 + 0 <= q) ? __expf(v.x - m) : 0.f;
    e.y = (k0 + 1 <= q) ? __expf(v.y - m) : 0.f;
    e.z = (k0 + 2 <= q) ? __expf(v.z - m) : 0.f;
    e.w = (k0 + 3 <= q) ? __expf(v.w - m) : 0.f;
    float s = e.x + e.y + e.z + e.w;
    #pragma unroll
    for (int o = 16; o > 0; o >>= 1) s += __shfl_xor_sync(0xffffffffu, s, o);
    if ((tid & 31) == 0) sm[tid >> 5] = s;
    __syncthreads();
    if (tid < 32) {
        float t = (tid < 8) ? sm[tid] : 0.f;
        #pragma unroll
        for (int o = 4; o > 0; o >>= 1) t += __shfl_xor_sync(0xffffffffu, t, o);
        if (tid == 0) sm[0] = t;
    }
    __syncthreads();
    const float inv = 1.f / sm[0];
    ((__half2*)p)[2 * tid]     = __floats2half2_rn(e.x * inv, e.y * inv);
    ((__half2*)p)[2 * tid + 1] = __floats2half2_rn(e.z * inv, e.w * inv);
}

// ---------------------------------------------------------------- Column sums (half attn, fp32 acc)
__global__ __launch_bounds__(256) void colsum_part_k(
    const __half* __restrict__ attn, float* __restrict__ part)
{
    const int k  = blockIdx.x * 256 + threadIdx.x;
    const int b  = blockIdx.y;
    const int rs = blockIdx.z;
    const int RC = Hh * Ss / RSPLIT;
    const __half* base = attn + (long long)b * Hh * Ss * Ss
                              + (long long)rs * RC * Ss + k;
    float s = 0.f;
    #pragma unroll 8
    for (int r = 0; r < RC; r++) s += __half2float(base[(long long)r * Ss]);
    part[(rs * Bb + b) * Ss + k] = s;
}

__global__ __launch_bounds__(256) void colsum_fin_k(
    const float* __restrict__ part, float* __restrict__ amap)
{
    const int i = blockIdx.x * 256 + threadIdx.x;
    float s = 0.f;
    #pragma unroll
    for (int rs = 0; rs < RSPLIT; rs++) s += part[rs * Bb * Ss + i];
    amap[i] += s;
}

// ---------------------------------------------------------------- misc
__global__ __launch_bounds__(256) void init_x_snap_k(
    const float4* __restrict__ token, float4* __restrict__ x,
    float4* __restrict__ st)
{
    const int i = blockIdx.x * 256 + threadIdx.x;
    float4 v = token[i];
    x[i] = v;
    st[((long long)(i >> 8) * DEPTH + 0) * 256 + (i & 255)] = v;
}

__global__ void zero_k(float* p, int n)
{
    int i = blockIdx.x * 256 + threadIdx.x;
    if (i < n) p[i] = 0.f;
}

// ---------------------------------------------------------------- launcher
extern "C" void kernel_launch(void* const* d_in, const int* in_sizes, int n_in,
                              void* d_out, int out_size)
{
    const float* token = (const float*)d_in[0];
    const float* Wq    = (const float*)d_in[1];
    const float* Wkv   = (const float*)d_in[2];
    const float* Wo    = (const float*)d_in[3];
    const float* b_o   = (const float*)d_in[4];
    const float* g1    = (const float*)d_in[5];
    const float* b1    = (const float*)d_in[6];
    const float* g3    = (const float*)d_in[7];
    const float* b3    = (const float*)d_in[8];
    const float* W1    = (const float*)d_in[9];
    const float* W2    = (const float*)d_in[10];
    const float* gout  = (const float*)d_in[11];
    const float* bout  = (const float*)d_in[12];
    float* out = (float*)d_out;

    float *x, *red, *part;
    __half *xn, *qkv, *wqkvT, *woT, *w1T, *w2T, *attn, *y, *ff;
    cudaGetSymbolAddress((void**)&x,     g_x);
    cudaGetSymbolAddress((void**)&xn,    g_xn);
    cudaGetSymbolAddress((void**)&qkv,   g_qkv);
    cudaGetSymbolAddress((void**)&wqkvT, g_wqkvT);
    cudaGetSymbolAddress((void**)&woT,   g_woT);
    cudaGetSymbolAddress((void**)&w1T,   g_w1T);
    cudaGetSymbolAddress((void**)&w2T,   g_w2T);
    cudaGetSymbolAddress((void**)&attn,  g_attn);
    cudaGetSymbolAddress((void**)&y,     g_y);
    cudaGetSymbolAddress((void**)&ff,    g_ff);
    cudaGetSymbolAddress((void**)&red,   g_red);
    cudaGetSymbolAddress((void**)&part,  g_part);

    cudaFuncSetAttribute(gemm_h<0, true,  true >, cudaFuncAttributeMaxDynamicSharedMemorySize, GEMM_SMEM);
    cudaFuncSetAttribute(gemm_h<0, true,  false>, cudaFuncAttributeMaxDynamicSharedMemorySize, GEMM_SMEM);
    cudaFuncSetAttribute(gemm_h<0, false, true >, cudaFuncAttributeMaxDynamicSharedMemorySize, GEMM_SMEM);
    cudaFuncSetAttribute(gemm_h<2, true,  true >, cudaFuncAttributeMaxDynamicSharedMemorySize, GEMM_SMEM);

    float* out_state = out + (size_t)BS * Dd;
    float* amap      = out_state + (size_t)BS * DEPTH * Dd;

    init_x_snap_k<<<BS * Dd / 4 / 256, 256>>>((const float4*)token, (float4*)x,
                                              (float4*)out_state);
    zero_k<<<(BS + 255) / 256, 256>>>(amap, BS);

    const int D3 = 3 * Dd;
    transpose_cvt_k<<<dim3(Dd / 32, Dd / 32, DEPTH), 256>>>(
        Wq, wqkvT, Dd, Dd, (long long)Dd * Dd, (long long)D3 * Dd);
    transpose_cvt_k<<<dim3(2 * Dd / 32, Dd / 32, DEPTH), 256>>>(
        Wkv, wqkvT + (size_t)Dd * Dd, Dd, 2 * Dd,
        (long long)Dd * 2 * Dd, (long long)D3 * Dd);
    transpose_cvt_k<<<dim3(Dd / 32, Dd / 32, DEPTH), 256>>>(
        Wo, woT, Dd, Dd, (long long)Dd * Dd, (long long)Dd * Dd);
    transpose_cvt_k<<<dim3(FF / 32, Dd / 32, DEPTH), 256>>>(
        W1, w1T, Dd, FF, (long long)Dd * FF, (long long)Dd * FF);
    transpose_cvt_k<<<dim3(Dd / 32, FF / 32, DEPTH), 256>>>(
        W2, w2T, FF, Dd, (long long)FF * Dd, (long long)FF * Dd);

    const float scale = rsqrtf((float)HD);
    const int NRED = BS * Dd / 4 / 256;

    for (int l = 0; l < DEPTH; l++) {
        // LN1 -> half xn
        ln_k<true><<<BS, 256>>>(x, g1 + l * Dd, b1 + l * Dd, xn);
        // QKV = xn @ [Wq|Wkv]^T  (TRANSB, half out)
        gemm_h<0, true, true><<<dim3(D3 / BN, BS / BM, 1), 128, GEMM_SMEM>>>(
            xn, wqkvT + (size_t)l * D3 * Dd, qkv,
            Dd, Dd, Dd, D3, 0, 0, 0, 0, 0, 0, 1, 1.f, 0);
        // scores = scale * Q @ K^T (TRANSB, half out, causal tile-skip)
        gemm_h<0, true, true><<<dim3(Ss / BN, Ss / BM, Bb * Hh), 128, GEMM_SMEM>>>(
            qkv, qkv + Dd, attn,
            HD, D3, D3, Ss,
            (long long)Ss * D3, HD,
            (long long)Ss * D3, HD,
            (long long)Hh * Ss * Ss, (long long)Ss * Ss,
            Hh, scale, 1);
        // softmax rows
        softmax_k<<<Bb * Hh * Ss, 256>>>(attn);
        // attention-map column sums
        colsum_part_k<<<dim3(Ss / 256, Bb, RSPLIT), 256>>>(attn, part);
        colsum_fin_k<<<Bb * Ss / 256, 256>>>(part, amap);
        // y = attn @ V (non-trans B, K-trim, half out)
        gemm_h<0, false, true><<<dim3(HD / BN, Ss / BM, Bb * Hh), 128, GEMM_SMEM>>>(
            attn, qkv + 2 * Dd, y,
            Ss, Ss, D3, Dd,
            (long long)Hh * Ss * Ss, (long long)Ss * Ss,
            (long long)Ss * D3, HD,
            (long long)Ss * Dd, HD,
            Hh, 1.f, 2);
        // x += y @ Wo + b_o  (TRANSB, split-K=2, fp32 partials)
        gemm_h<0, true, false><<<dim3(Dd / BN, BS / BM, 2), 128, GEMM_SMEM>>>(
            y, woT + (size_t)l * Dd * Dd, red,
            Dd / 2, Dd, Dd, Dd,
            0, Dd / 2, 0, Dd / 2,
            0, (long long)BS * Dd,
            2, 1.f, 0);
        reduce_add_k<2, true, false><<<NRED, 256>>>(
            (const float4*)red, (float4*)x, b_o + l * Dd, nullptr, 0);
        // LN2 -> half xn
        ln_k<true><<<BS, 256>>>(x, g3 + l * Dd, b3 + l * Dd, xn);
        // ff = gelu(xn @ W1^T)  (TRANSB, half out)
        gemm_h<2, true, true><<<dim3(FF / BN, BS / BM, 1), 128, GEMM_SMEM>>>(
            xn, w1T + (size_t)l * FF * Dd, ff,
            Dd, Dd, Dd, FF, 0, 0, 0, 0, 0, 0, 1, 1.f, 0);
        // x += ff @ W2^T  (TRANSB, split-K=4, fp32 partials)
        gemm_h<0, true, false><<<dim3(Dd / BN, BS / BM, 4), 128, GEMM_SMEM>>>(
            ff, w2T + (size_t)l * Dd * FF, red,
            FF / 4, FF, FF, Dd,
            0, FF / 4, 0, FF / 4,
            0, (long long)BS * Dd,
            4, 1.f, 0);
        if (l < DEPTH - 1)
            reduce_add_k<4, false, true><<<NRED, 256>>>(
                (const float4*)red, (float4*)x, nullptr, (float4*)out_state, l + 1);
        else
            reduce_add_k<4, false, false><<<NRED, 256>>>(
                (const float4*)red, (float4*)x, nullptr, nullptr, 0);
    }
    // final LN -> x_out (fp32)
    ln_k<false><<<BS, 256>>>(x, gout, bout, out);
}

// round 11
// speedup vs baseline: 1.0134x; 1.0134x over previous
#include <cuda_runtime.h>
#include <cuda_fp16.h>
#include <math.h>
#include <stdint.h>

// Problem constants
constexpr int Bb    = 2;
constexpr int Ss    = 1024;
constexpr int Dd    = 1024;
constexpr int Hh    = 8;
constexpr int HD    = 128;
constexpr int DEPTH = 8;
constexpr int FF    = 4096;
constexpr int BS    = Bb * Ss;      // 2048
constexpr int RSPLIT = 32;

// Scratch (device globals: allocation-free)
__device__ float  g_x  [BS * Dd];
__device__ __half g_xn [BS * Dd];
__device__ __half g_qkv[(size_t)BS * 3 * Dd];            // q | k | v packed (half)
__device__ __half g_wqkvT[(size_t)DEPTH * 3 * Dd * Dd];  // [Wq|Wkv]^T [3D][D] half
__device__ __half g_woT [(size_t)DEPTH * Dd * Dd];       // Wo^T  [D][D] half
__device__ __half g_w1T [(size_t)DEPTH * FF * Dd];       // W1^T  [FF][D] half
__device__ __half g_w2T [(size_t)DEPTH * Dd * FF];       // W2^T  [D][FF] half
__device__ __half g_attn[(size_t)Bb * Hh * Ss * Ss];     // 32 MB
__device__ __half g_y  [BS * Dd];
__device__ __half g_ff [(size_t)BS * FF];
__device__ float  g_red[(size_t)4 * BS * Dd];            // split-K partials (fp32)
__device__ float  g_part[RSPLIT * Bb * Ss];

// ---------------------------------------------------------------- mma / ldmatrix
__device__ __forceinline__ void mma_f16(float* c, const unsigned* a, const unsigned* b) {
    asm volatile(
        "mma.sync.aligned.m16n8k16.row.col.f32.f16.f16.f32 "
        "{%0,%1,%2,%3}, {%4,%5,%6,%7}, {%8,%9}, {%0,%1,%2,%3};"
        : "+f"(c[0]), "+f"(c[1]), "+f"(c[2]), "+f"(c[3])
        : "r"(a[0]), "r"(a[1]), "r"(a[2]), "r"(a[3]), "r"(b[0]), "r"(b[1]));
}
__device__ __forceinline__ void ldsm4(unsigned& r0, unsigned& r1, unsigned& r2,
                                      unsigned& r3, unsigned addr) {
    asm volatile("ldmatrix.sync.aligned.m8n8.x4.shared.b16 {%0,%1,%2,%3}, [%4];"
                 : "=r"(r0), "=r"(r1), "=r"(r2), "=r"(r3) : "r"(addr));
}
__device__ __forceinline__ void ldsm4t(unsigned& r0, unsigned& r1, unsigned& r2,
                                       unsigned& r3, unsigned addr) {
    asm volatile("ldmatrix.sync.aligned.m8n8.x4.trans.shared.b16 {%0,%1,%2,%3}, [%4];"
                 : "=r"(r0), "=r"(r1), "=r"(r2), "=r"(r3) : "r"(addr));
}
__device__ __forceinline__ void cp_async16(unsigned saddr, const void* gptr) {
    asm volatile("cp.async.cg.shared.global [%0], [%1], 16;"
                 :: "r"(saddr), "l"(gptr));
}
#define CP_COMMIT() asm volatile("cp.async.commit_group;")
#define CP_WAIT2()  asm volatile("cp.async.wait_group 2;")

// ---------------------------------------------------------------- fp16 tensor-core GEMM
// (R9 configuration: 4 stages, 2 CTAs/SM — proven 2667us)
#define BM 128
#define BN 128
#define BKH 32          // halves per k-tile
#define AL 40           // A / B(trans) row length in halves: 80B rows, conflict-free ldsm
#define BLN 136         // B(non-trans) [k][n] row length in halves
#define STAGES 4
constexpr int AH_ST = BM * AL;                 // 5120 halves
constexpr int BH_ST = 5120;                    // max(128*40, 32*136)
constexpr int GEMM_SMEM = STAGES * (AH_ST + BH_ST) * 2;   // 81920 B

template<int EPI, bool TRANSB, bool OUTHALF>
__global__ __launch_bounds__(128, 2) void gemm_h(
    const __half* __restrict__ A, const __half* __restrict__ Bg,
    void* __restrict__ Cv,
    int K, int lda, int ldb, int ldc,
    long long sAo, long long sAi, long long sBo, long long sBi,
    long long sCo, long long sCi, int zdiv,
    float alpha, int causal)
{
    const int bm = blockIdx.y * BM;
    const int bn = blockIdx.x * BN;
    if (causal == 1 && bn >= bm + BM) return;
    const int Keff = (causal == 2) ? min(K, bm + BM) : K;

    const int z  = blockIdx.z;
    const int zo = z / zdiv;
    const int zi = z - zo * zdiv;
    A  += zo * sAo + zi * sAi;
    Bg += zo * sBo + zi * sBi;
    const long long coff = zo * sCo + zi * sCi;
    __half* Ch = (__half*)Cv + coff;
    float*  Cf = (float*)Cv + coff;

    extern __shared__ __align__(16) char smem_raw[];
    const unsigned asb = (unsigned)__cvta_generic_to_shared(smem_raw);
    const unsigned bsb = asb + (unsigned)(STAGES * AH_ST * 2);

    const int tid  = threadIdx.x;
    const int lane = tid & 31;
    const int warp = tid >> 5;
    const int wm   = (warp & 1) * 64;       // warp tile 64(M) x 64(N)
    const int wn   = (warp >> 1) * 64;
    const int g    = lane >> 2;
    const int t    = lane & 3;

    const int lp = lane >> 3;
    const int lr = lane & 7;
    const int aRowOff  = (lp & 1) * 8 + lr;
    const int aColOff  = (lp >> 1) * 8;         // halves
    const int bRowOff  = (lp >> 1) * 8 + lr;    // trans-B frag (n rows)
    const int bColOff  = (lp & 1) * 8;
    const int ntRowOff = (lp & 1) * 8 + lr;     // non-trans B (k rows)
    const int ntColOff = (lp >> 1) * 8;

    float acc[4][8][4];
    #pragma unroll
    for (int i = 0; i < 4; i++)
        #pragma unroll
        for (int j = 0; j < 8; j++)
            #pragma unroll
            for (int r = 0; r < 4; r++) acc[i][j][r] = 0.f;

    auto issue = [&](int s, int k0) {
        const unsigned aB = asb + (unsigned)(s * AH_ST * 2);
        #pragma unroll
        for (int h = 0; h < 4; h++) {
            int row = (tid >> 2) + 32 * h;
            cp_async16(aB + (unsigned)((row * AL + (tid & 3) * 8) * 2),
                       &A[(long long)(bm + row) * lda + k0 + (tid & 3) * 8]);
        }
        const unsigned bB = bsb + (unsigned)(s * BH_ST * 2);
        if (TRANSB) {
            #pragma unroll
            for (int h = 0; h < 4; h++) {
                int row = (tid >> 2) + 32 * h;
                cp_async16(bB + (unsigned)((row * AL + (tid & 3) * 8) * 2),
                           &Bg[(long long)(bn + row) * ldb + k0 + (tid & 3) * 8]);
            }
        } else {
            #pragma unroll
            for (int h = 0; h < 4; h++) {
                int idx = h * 128 + tid;
                int kr  = idx >> 4;
                int ch  = idx & 15;
                cp_async16(bB + (unsigned)((kr * BLN + ch * 8) * 2),
                           &Bg[(long long)(k0 + kr) * ldb + bn + ch * 8]);
            }
        }
    };

    auto compute = [&](int p) {
        const unsigned abase = asb + (unsigned)(p * AH_ST * 2)
                             + (unsigned)(((wm + aRowOff) * AL + aColOff) * 2);
        unsigned bbase;
        if (TRANSB)
            bbase = bsb + (unsigned)(p * BH_ST * 2)
                  + (unsigned)(((wn + bRowOff) * AL + bColOff) * 2);
        else
            bbase = bsb + (unsigned)(p * BH_ST * 2)
                  + (unsigned)((ntRowOff * BLN + wn + ntColOff) * 2);
        #pragma unroll
        for (int ks = 0; ks < 2; ks++) {
            const int kk = ks * 16;
            unsigned af[4][4], bf[8][2];
            #pragma unroll
            for (int i = 0; i < 4; i++)
                ldsm4(af[i][0], af[i][1], af[i][2], af[i][3],
                      abase + (unsigned)((i * 16 * AL + kk) * 2));
            if (TRANSB) {
                #pragma unroll
                for (int jp = 0; jp < 4; jp++) {
                    unsigned r0, r1, r2, r3;
                    ldsm4(r0, r1, r2, r3, bbase + (unsigned)((jp * 16 * AL + kk) * 2));
                    bf[2 * jp][0] = r0; bf[2 * jp][1] = r1;
                    bf[2 * jp + 1][0] = r2; bf[2 * jp + 1][1] = r3;
                }
            } else {
                #pragma unroll
                for (int jp = 0; jp < 4; jp++) {
                    unsigned r0, r1, r2, r3;
                    ldsm4t(r0, r1, r2, r3,
                           bbase + (unsigned)((kk * BLN + jp * 16) * 2));
                    bf[2 * jp][0] = r0; bf[2 * jp][1] = r1;
                    bf[2 * jp + 1][0] = r2; bf[2 * jp + 1][1] = r3;
                }
            }
            #pragma unroll
            for (int i = 0; i < 4; i++)
                #pragma unroll
                for (int j = 0; j < 8; j++)
                    mma_f16(acc[i][j], af[i], bf[j]);
        }
    };

    const int nk = Keff / BKH;
    #pragma unroll
    for (int s = 0; s < STAGES - 1; s++) {
        if (s < nk) issue(s, s * BKH);
        CP_COMMIT();
    }
    for (int kt = 0; kt < nk; kt++) {
        CP_WAIT2();
        __syncthreads();
        compute(kt % STAGES);
        if (kt + STAGES - 1 < nk)
            issue((kt + STAGES - 1) % STAGES, (kt + STAGES - 1) * BKH);
        CP_COMMIT();
    }

    // Epilogue
    #pragma unroll
    for (int i = 0; i < 4; i++) {
        #pragma unroll
        for (int j = 0; j < 8; j++) {
            const long long row = bm + wm + i * 16 + g;
            const int       col = bn + wn + j * 8 + 2 * t;
            float2 v0 = make_float2(acc[i][j][0] * alpha, acc[i][j][1] * alpha);
            float2 v1 = make_float2(acc[i][j][2] * alpha, acc[i][j][3] * alpha);
            if (EPI == 2) {
                const float c = 0.70710678118654752f;
                v0.x = 0.5f * v0.x * erfcf(-v0.x * c);
                v0.y = 0.5f * v0.y * erfcf(-v0.y * c);
                v1.x = 0.5f * v1.x * erfcf(-v1.x * c);
                v1.y = 0.5f * v1.y * erfcf(-v1.y * c);
            }
            if (OUTHALF) {
                *(__half2*)&Ch[row * (long long)ldc + col]       = __floats2half2_rn(v0.x, v0.y);
                *(__half2*)&Ch[(row + 8) * (long long)ldc + col] = __floats2half2_rn(v1.x, v1.y);
            } else {
                *(float2*)&Cf[row * (long long)ldc + col]       = v0;
                *(float2*)&Cf[(row + 8) * (long long)ldc + col] = v1;
            }
        }
    }
}

// ---------------------------------------------------------------- fused split-K reduce (+bias)(+snapshot)(+LN -> half xn)
// One block per row (Dd floats = 256 float4).
template<int P, bool BIAS, bool SNAP, bool OUTLN>
__global__ __launch_bounds__(256) void reduce_ln_k(
    const float4* __restrict__ part, float4* __restrict__ x,
    const float* __restrict__ bias, float4* __restrict__ st, int layer,
    const float* __restrict__ g, const float* __restrict__ b,
    __half* __restrict__ xn)
{
    __shared__ float sm0[8], sm1[8];
    const int row = blockIdx.x, tid = threadIdx.x;
    const int i = row * 256 + tid;
    constexpr int N4 = BS * Dd / 4;

    float4 s = part[i];
    #pragma unroll
    for (int p = 1; p < P; p++) {
        float4 v = part[(size_t)p * N4 + i];
        s.x += v.x; s.y += v.y; s.z += v.z; s.w += v.w;
    }
    if (BIAS) {
        float4 bb = ((const float4*)bias)[tid];
        s.x += bb.x; s.y += bb.y; s.z += bb.z; s.w += bb.w;
    }
    float4 v = x[i];
    v.x += s.x; v.y += s.y; v.z += s.z; v.w += s.w;
    x[i] = v;
    if (SNAP)
        st[((long long)row * DEPTH + layer) * 256 + tid] = v;

    if (OUTLN) {
        float su  = v.x + v.y + v.z + v.w;
        float su2 = v.x * v.x + v.y * v.y + v.z * v.z + v.w * v.w;
        #pragma unroll
        for (int o = 16; o > 0; o >>= 1) {
            su  += __shfl_xor_sync(0xffffffffu, su,  o);
            su2 += __shfl_xor_sync(0xffffffffu, su2, o);
        }
        if ((tid & 31) == 0) { sm0[tid >> 5] = su; sm1[tid >> 5] = su2; }
        __syncthreads();
        if (tid < 32) {
            su  = (tid < 8) ? sm0[tid] : 0.f;
            su2 = (tid < 8) ? sm1[tid] : 0.f;
            #pragma unroll
            for (int o = 4; o > 0; o >>= 1) {
                su  += __shfl_xor_sync(0xffffffffu, su,  o);
                su2 += __shfl_xor_sync(0xffffffffu, su2, o);
            }
            if (tid == 0) { sm0[0] = su; sm1[0] = su2; }
        }
        __syncthreads();
        const float mean = sm0[0] * (1.f / Dd);
        const float var  = sm1[0] * (1.f / Dd) - mean * mean;
        const float rstd = rsqrtf(var + 1e-5f);
        float4 gg = ((const float4*)g)[tid];
        float4 bb = ((const float4*)b)[tid];
        float4 o;
        o.x = (v.x - mean) * rstd * gg.x + bb.x;
        o.y = (v.y - mean) * rstd * gg.y + bb.y;
        o.z = (v.z - mean) * rstd * gg.z + bb.z;
        o.w = (v.w - mean) * rstd * gg.w + bb.w;
        __half2* oh = (__half2*)(xn + (long long)row * Dd);
        oh[2 * tid]     = __floats2half2_rn(o.x, o.y);
        oh[2 * tid + 1] = __floats2half2_rn(o.z, o.w);
    }
}

// ---------------------------------------------------------------- transpose + cvt to half
__global__ __launch_bounds__(256) void transpose_cvt_k(
    const float* __restrict__ src, __half* __restrict__ dst,
    int R, int C, long long sSrc, long long sDst)
{
    __shared__ float tile[32][33];
    src += blockIdx.z * sSrc;
    dst += blockIdx.z * sDst;
    const int c0 = blockIdx.x * 32, r0 = blockIdx.y * 32;
    const int tx = threadIdx.x & 31, ty = threadIdx.x >> 5;
    #pragma unroll
    for (int dy = 0; dy < 32; dy += 8)
        tile[ty + dy][tx] = src[(long long)(r0 + ty + dy) * C + c0 + tx];
    __syncthreads();
    #pragma unroll
    for (int dy = 0; dy < 32; dy += 8)
        dst[(long long)(c0 + ty + dy) * R + r0 + tx] = __float2half_rn(tile[tx][ty + dy]);
}

// ---------------------------------------------------------------- LayerNorm (standalone: layer-0 LN1, final LN)
template<bool OUTH>
__global__ __launch_bounds__(256) void ln_k(
    const float* __restrict__ x, const float* __restrict__ g,
    const float* __restrict__ b, void* __restrict__ outv)
{
    __shared__ float sm0[8], sm1[8];
    const int row = blockIdx.x, tid = threadIdx.x;
    float4 v = ((const float4*)(x + (long long)row * Dd))[tid];
    float s  = v.x + v.y + v.z + v.w;
    float s2 = v.x * v.x + v.y * v.y + v.z * v.z + v.w * v.w;
    #pragma unroll
    for (int o = 16; o > 0; o >>= 1) {
        s  += __shfl_xor_sync(0xffffffffu, s,  o);
        s2 += __shfl_xor_sync(0xffffffffu, s2, o);
    }
    if ((tid & 31) == 0) { sm0[tid >> 5] = s; sm1[tid >> 5] = s2; }
    __syncthreads();
    if (tid < 32) {
        s  = (tid < 8) ? sm0[tid] : 0.f;
        s2 = (tid < 8) ? sm1[tid] : 0.f;
        #pragma unroll
        for (int o = 4; o > 0; o >>= 1) {
            s  += __shfl_xor_sync(0xffffffffu, s,  o);
            s2 += __shfl_xor_sync(0xffffffffu, s2, o);
        }
        if (tid == 0) { sm0[0] = s; sm1[0] = s2; }
    }
    __syncthreads();
    const float mean = sm0[0] * (1.f / Dd);
    const float var  = sm1[0] * (1.f / Dd) - mean * mean;
    const float rstd = rsqrtf(var + 1e-5f);
    float4 gg = ((const float4*)g)[tid];
    float4 bb = ((const float4*)b)[tid];
    float4 o;
    o.x = (v.x - mean) * rstd * gg.x + bb.x;
    o.y = (v.y - mean) * rstd * gg.y + bb.y;
    o.z = (v.z - mean) * rstd * gg.z + bb.z;
    o.w = (v.w - mean) * rstd * gg.w + bb.w;
    if (OUTH) {
        __half2* oh = (__half2*)((__half*)outv + (long long)row * Dd);
        oh[2 * tid]     = __floats2half2_rn(o.x, o.y);
        oh[2 * tid + 1] = __floats2half2_rn(o.z, o.w);
    } else {
        ((float4*)((float*)outv + (long long)row * Dd))[tid] = o;
    }
}

// ---------------------------------------------------------------- Softmax (half in/out, fp32 math)
__global__ __launch_bounds__(256) void softmax_k(__half* __restrict__ attn)
{
    __shared__ float sm[8];
    const int row = blockIdx.x;
    const int q   = row & (Ss - 1);
    __half* p = attn + (long long)row * Ss;
    const int tid = threadIdx.x;
    const int k0  = tid * 4;
    __half2 h0 = ((const __half2*)p)[2 * tid];
    __half2 h1 = ((const __half2*)p)[2 * tid + 1];
    float4 v = make_float4(__low2float(h0), __high2float(h0),
                           __low2float(h1), __high2float(h1));

    float m = -1e30f;
    if (k0 + 0 <= q) m = fmaxf(m, v.x);
    if (k0 + 1 <= q) m = fmaxf(m, v.y);
    if (k0 + 2 <= q) m = fmaxf(m, v.z);
    if (k0 + 3 <= q) m = fmaxf(m, v.w);
    #pragma unroll
    for (int o = 16; o > 0; o >>= 1) m = fmaxf(m, __shfl_xor_sync(0xffffffffu, m, o));
    if ((tid & 31) == 0) sm[tid >> 5] = m;
    __syncthreads();
    if (tid < 32) {
        float t = (tid < 8) ? sm[tid] : -1e30f;
        #pragma unroll
        for (int o = 4; o > 0; o >>= 1) t = fmaxf(t, __shfl_xor_sync(0xffffffffu, t, o));
        if (tid == 0) sm[0] = t;
    }
    __syncthreads();
    m = sm[0];
    __syncthreads();

    float4 e;
    e.x = (k0 + 0 <= q) ? __expf(v.x - m) : 0.f;
    e.y = (k0 + 1 <= q) ? __expf(v.y - m) : 0.f;
    e.z = (k0 + 2 <= q) ? __expf(v.z - m) : 0.f;
    e.w = (k0 + 3 <= q) ? __expf(v.w - m) : 0.f;
    float s = e.x + e.y + e.z + e.w;
    #pragma unroll
    for (int o = 16; o > 0; o >>= 1) s += __shfl_xor_sync(0xffffffffu, s, o);
    if ((tid & 31) == 0) sm[tid >> 5] = s;
    __syncthreads();
    if (tid < 32) {
        float t = (tid < 8) ? sm[tid] : 0.f;
        #pragma unroll
        for (int o = 4; o > 0; o >>= 1) t += __shfl_xor_sync(0xffffffffu, t, o);
        if (tid == 0) sm[0] = t;
    }
    __syncthreads();
    const float inv = 1.f / sm[0];
    ((__half2*)p)[2 * tid]     = __floats2half2_rn(e.x * inv, e.y * inv);
    ((__half2*)p)[2 * tid + 1] = __floats2half2_rn(e.z * inv, e.w * inv);
}

// ---------------------------------------------------------------- Column sums (causal-trimmed)
__global__ __launch_bounds__(256) void colsum_part_k(
    const __half* __restrict__ attn, float* __restrict__ part)
{
    const int k  = blockIdx.x * 256 + threadIdx.x;   // 0..1023
    const int b  = blockIdx.y;
    const int rs = blockIdx.z;
    const int RC = Hh * Ss / RSPLIT;                 // 256 consecutive q within one head
    const int q0 = (rs & 3) * 256;                   // first q in this split
    const __half* base = attn + (long long)b * Hh * Ss * Ss
                              + (long long)rs * RC * Ss + k;
    int r0c = k - q0;
    r0c = r0c < 0 ? 0 : (r0c > RC ? RC : r0c);       // rows with q >= k only
    float s = 0.f;
    for (int r = r0c; r < RC; r++) s += __half2float(base[(long long)r * Ss]);
    part[(rs * Bb + b) * Ss + k] = s;
}

__global__ __launch_bounds__(256) void colsum_fin_k(
    const float* __restrict__ part, float* __restrict__ amap)
{
    const int i = blockIdx.x * 256 + threadIdx.x;
    float s = 0.f;
    #pragma unroll
    for (int rs = 0; rs < RSPLIT; rs++) s += part[rs * Bb * Ss + i];
    amap[i] += s;
}

// ---------------------------------------------------------------- misc
__global__ __launch_bounds__(256) void init_x_snap_k(
    const float4* __restrict__ token, float4* __restrict__ x,
    float4* __restrict__ st)
{
    const int i = blockIdx.x * 256 + threadIdx.x;
    float4 v = token[i];
    x[i] = v;
    st[((long long)(i >> 8) * DEPTH + 0) * 256 + (i & 255)] = v;
}

__global__ void zero_k(float* p, int n)
{
    int i = blockIdx.x * 256 + threadIdx.x;
    if (i < n) p[i] = 0.f;
}

// ---------------------------------------------------------------- launcher
extern "C" void kernel_launch(void* const* d_in, const int* in_sizes, int n_in,
                              void* d_out, int out_size)
{
    const float* token = (const float*)d_in[0];
    const float* Wq    = (const float*)d_in[1];
    const float* Wkv   = (const float*)d_in[2];
    const float* Wo    = (const float*)d_in[3];
    const float* b_o   = (const float*)d_in[4];
    const float* g1    = (const float*)d_in[5];
    const float* b1    = (const float*)d_in[6];
    const float* g3    = (const float*)d_in[7];
    const float* b3    = (const float*)d_in[8];
    const float* W1    = (const float*)d_in[9];
    const float* W2    = (const float*)d_in[10];
    const float* gout  = (const float*)d_in[11];
    const float* bout  = (const float*)d_in[12];
    float* out = (float*)d_out;

    float *x, *red, *part;
    __half *xn, *qkv, *wqkvT, *woT, *w1T, *w2T, *attn, *y, *ff;
    cudaGetSymbolAddress((void**)&x,     g_x);
    cudaGetSymbolAddress((void**)&xn,    g_xn);
    cudaGetSymbolAddress((void**)&qkv,   g_qkv);
    cudaGetSymbolAddress((void**)&wqkvT, g_wqkvT);
    cudaGetSymbolAddress((void**)&woT,   g_woT);
    cudaGetSymbolAddress((void**)&w1T,   g_w1T);
    cudaGetSymbolAddress((void**)&w2T,   g_w2T);
    cudaGetSymbolAddress((void**)&attn,  g_attn);
    cudaGetSymbolAddress((void**)&y,     g_y);
    cudaGetSymbolAddress((void**)&ff,    g_ff);
    cudaGetSymbolAddress((void**)&red,   g_red);
    cudaGetSymbolAddress((void**)&part,  g_part);

    cudaFuncSetAttribute(gemm_h<0, true,  true >, cudaFuncAttributeMaxDynamicSharedMemorySize, GEMM_SMEM);
    cudaFuncSetAttribute(gemm_h<0, true,  false>, cudaFuncAttributeMaxDynamicSharedMemorySize, GEMM_SMEM);
    cudaFuncSetAttribute(gemm_h<0, false, true >, cudaFuncAttributeMaxDynamicSharedMemorySize, GEMM_SMEM);
    cudaFuncSetAttribute(gemm_h<2, true,  true >, cudaFuncAttributeMaxDynamicSharedMemorySize, GEMM_SMEM);

    float* out_state = out + (size_t)BS * Dd;
    float* amap      = out_state + (size_t)BS * DEPTH * Dd;

    init_x_snap_k<<<BS * Dd / 4 / 256, 256>>>((const float4*)token, (float4*)x,
                                              (float4*)out_state);
    zero_k<<<(BS + 255) / 256, 256>>>(amap, BS);

    const int D3 = 3 * Dd;
    transpose_cvt_k<<<dim3(Dd / 32, Dd / 32, DEPTH), 256>>>(
        Wq, wqkvT, Dd, Dd, (long long)Dd * Dd, (long long)D3 * Dd);
    transpose_cvt_k<<<dim3(2 * Dd / 32, Dd / 32, DEPTH), 256>>>(
        Wkv, wqkvT + (size_t)Dd * Dd, Dd, 2 * Dd,
        (long long)Dd * 2 * Dd, (long long)D3 * Dd);
    transpose_cvt_k<<<dim3(Dd / 32, Dd / 32, DEPTH), 256>>>(
        Wo, woT, Dd, Dd, (long long)Dd * Dd, (long long)Dd * Dd);
    transpose_cvt_k<<<dim3(FF / 32, Dd / 32, DEPTH), 256>>>(
        W1, w1T, Dd, FF, (long long)Dd * FF, (long long)Dd * FF);
    transpose_cvt_k<<<dim3(Dd / 32, FF / 32, DEPTH), 256>>>(
        W2, w2T, FF, Dd, (long long)FF * Dd, (long long)FF * Dd);

    const float scale = rsqrtf((float)HD);

    // layer-0 LN1 (later LN1s are fused into the FF2 reduce)
    ln_k<true><<<BS, 256>>>(x, g1, b1, xn);

    for (int l = 0; l < DEPTH; l++) {
        // QKV = xn @ [Wq|Wkv]^T
        gemm_h<0, true, true><<<dim3(D3 / BN, BS / BM, 1), 128, GEMM_SMEM>>>(
            xn, wqkvT + (size_t)l * D3 * Dd, qkv,
            Dd, Dd, Dd, D3, 0, 0, 0, 0, 0, 0, 1, 1.f, 0);
        // scores = scale * Q @ K^T (causal tile-skip)
        gemm_h<0, true, true><<<dim3(Ss / BN, Ss / BM, Bb * Hh), 128, GEMM_SMEM>>>(
            qkv, qkv + Dd, attn,
            HD, D3, D3, Ss,
            (long long)Ss * D3, HD,
            (long long)Ss * D3, HD,
            (long long)Hh * Ss * Ss, (long long)Ss * Ss,
            Hh, scale, 1);
        // softmax rows
        softmax_k<<<Bb * Hh * Ss, 256>>>(attn);
        // attention-map column sums (causal-trimmed)
        colsum_part_k<<<dim3(Ss / 256, Bb, RSPLIT), 256>>>(attn, part);
        colsum_fin_k<<<Bb * Ss / 256, 256>>>(part, amap);
        // y = attn @ V (K-trim)
        gemm_h<0, false, true><<<dim3(HD / BN, Ss / BM, Bb * Hh), 128, GEMM_SMEM>>>(
            attn, qkv + 2 * Dd, y,
            Ss, Ss, D3, Dd,
            (long long)Hh * Ss * Ss, (long long)Ss * Ss,
            (long long)Ss * D3, HD,
            (long long)Ss * Dd, HD,
            Hh, 1.f, 2);
        // Wo GEMM (split-K=2, fp32 partials)
        gemm_h<0, true, false><<<dim3(Dd / BN, BS / BM, 2), 128, GEMM_SMEM>>>(
            y, woT + (size_t)l * Dd * Dd, red,
            Dd / 2, Dd, Dd, Dd,
            0, Dd / 2, 0, Dd / 2,
            0, (long long)BS * Dd,
            2, 1.f, 0);
        // fused: x += partials + b_o ; xn = LN2(x)
        reduce_ln_k<2, true, false, true><<<BS, 256>>>(
            (const float4*)red, (float4*)x, b_o + l * Dd, nullptr, 0,
            g3 + l * Dd, b3 + l * Dd, xn);
        // ff = gelu(xn @ W1^T)
        gemm_h<2, true, true><<<dim3(FF / BN, BS / BM, 1), 128, GEMM_SMEM>>>(
            xn, w1T + (size_t)l * FF * Dd, ff,
            Dd, Dd, Dd, FF, 0, 0, 0, 0, 0, 0, 1, 1.f, 0);
        // FF2 GEMM (split-K=4, fp32 partials)
        gemm_h<0, true, false><<<dim3(Dd / BN, BS / BM, 4), 128, GEMM_SMEM>>>(
            ff, w2T + (size_t)l * Dd * FF, red,
            FF / 4, FF, FF, Dd,
            0, FF / 4, 0, FF / 4,
            0, (long long)BS * Dd,
            4, 1.f, 0);
        // fused: x += partials ; snapshot(l+1) ; xn = LN1_{l+1}(x)
        if (l < DEPTH - 1)
            reduce_ln_k<4, false, true, true><<<BS, 256>>>(
                (const float4*)red, (float4*)x, nullptr, (float4*)out_state, l + 1,
                g1 + (l + 1) * Dd, b1 + (l + 1) * Dd, xn);
        else
            reduce_ln_k<4, false, false, false><<<BS, 256>>>(
                (const float4*)red, (float4*)x, nullptr, nullptr, 0,
                nullptr, nullptr, nullptr);
    }
    // final LN -> x_out (fp32)
    ln_k<false><<<BS, 256>>>(x, gout, bout, out);
}